// round 5
// baseline (speedup 1.0000x reference)
#include <cuda_runtime.h>
#include <cstdint>

#define TILE        128
#define BLOCK_T     128
#define STAGES      2
#define F4_PER_TILE (TILE * 25)                   // 3200 float4
#define TILE_BYTES  (F4_PER_TILE * 16)            // 51200
#define SMEM_BYTES  (STAGES * TILE_BYTES)         // 102400 -> 2 blocks/SM

__device__ __forceinline__ void cp_async16(void* smem_dst, const void* gsrc) {
    uint32_t d = (uint32_t)__cvta_generic_to_shared(smem_dst);
    asm volatile("cp.async.cg.shared.global [%0], [%1], 16;\n" :: "r"(d), "l"(gsrc));
}

__global__ void __launch_bounds__(BLOCK_T, 2) fused_kernel(
    const float4* __restrict__ x4,
    const float* __restrict__ A_real,
    const float* __restrict__ A_imag,
    const float* __restrict__ psi_real,
    const float* __restrict__ psi_imag,
    float2* __restrict__ out,
    int batch, int ntiles)
{
    extern __shared__ __align__(128) float4 sx[];   // [STAGES][F4_PER_TILE]
    __shared__ __align__(16) float sMf[200];

    int tid   = threadIdx.x;
    int nblk  = gridDim.x;
    int first = blockIdx.x;

    // Prefetch helper: stage one tile via cp.async (25 x 16B per thread).
    auto prefetch = [&](int t, int s) {
        const float4* src = x4 + (size_t)t * F4_PER_TILE;
        float4* dst = sx + s * F4_PER_TILE;
        if (t < ntiles - 1) {
            #pragma unroll
            for (int r = 0; r < 25; r++) {
                int i = r * BLOCK_T + tid;
                cp_async16(dst + i, src + i);
            }
        } else {
            int limit = batch * 25 - t * F4_PER_TILE;
            #pragma unroll
            for (int r = 0; r < 25; r++) {
                int i = r * BLOCK_T + tid;
                if (i < limit) cp_async16(dst + i, src + i);
            }
        }
        asm volatile("cp.async.commit_group;\n");
    };

    // Prologue: enqueue both stages before doing anything else.
    if (first < ntiles)            prefetch(first, 0);
    else                           asm volatile("cp.async.commit_group;\n");
    if (first + nblk < ntiles)     prefetch(first + nblk, 1);
    else                           asm volatile("cp.async.commit_group;\n");

    // Fused stage 1: M[k,a] = sum_ij (P_re A_real - P_im A_imag), hidden
    // under the first tile's flight. Each thread owns up to 2 (k,a) entries.
    {
        float pr[10], pi[10];
        #pragma unroll
        for (int q = 0; q < 10; q++) { pr[q] = psi_real[q]; pi[q] = psi_imag[q]; }
        #pragma unroll
        for (int e = 0; e < 2; e++) {
            int idx200 = tid + e * BLOCK_T;     // 0..255, valid < 200
            if (idx200 < 200) {
                int k = idx200 / 100, a = idx200 - k * 100;
                float acc = 0.0f;
                #pragma unroll
                for (int i = 0; i < 10; i++) {
                    #pragma unroll
                    for (int j = 0; j < 10; j++) {
                        float Pre = pr[i] * pr[j] + pi[i] * pi[j];
                        float Pim = pr[i] * pi[j] - pi[i] * pr[j];
                        int idx = ((k * 10 + i) * 10 + j) * 100 + a;
                        acc = fmaf(Pre, A_real[idx], acc);
                        acc = fmaf(-Pim, A_imag[idx], acc);
                    }
                }
                sMf[idx200] = acc;
            }
        }
    }
    __syncthreads();                            // sMf visible to all
    const float4* sM4 = reinterpret_cast<const float4*>(sMf);   // [50]

    int cnt = 0;
    for (int t = first; t < ntiles; t += nblk, cnt++) {
        int s = cnt & 1;
        int tn = t + STAGES * nblk;
        // Wait for stage s's copy; keep the other stage's copy in flight.
        asm volatile("cp.async.wait_group 1;\n");
        __syncthreads();

        int row = t * TILE + tid;
        float s0 = 0.0f, s1 = 0.0f;
        const float4* xr = sx + s * F4_PER_TILE + tid * 25;
        #pragma unroll
        for (int i = 0; i < 25; i++) {
            float4 v  = xr[i];
            float4 m0 = sM4[i];
            float4 m1 = sM4[25 + i];
            s0 = fmaf(v.x, m0.x, s0); s0 = fmaf(v.y, m0.y, s0);
            s0 = fmaf(v.z, m0.z, s0); s0 = fmaf(v.w, m0.w, s0);
            s1 = fmaf(v.x, m1.x, s1); s1 = fmaf(v.y, m1.y, s1);
            s1 = fmaf(v.z, m1.z, s1); s1 = fmaf(v.w, m1.w, s1);
        }
        if (row < batch) out[row] = make_float2(s0, s1);
        __syncthreads();                        // stage s fully consumed

        if (tn < ntiles) prefetch(tn, s);
        else             asm volatile("cp.async.commit_group;\n");
    }
}

extern "C" void kernel_launch(void* const* d_in, const int* in_sizes, int n_in,
                              void* d_out, int out_size) {
    const float* x        = (const float*)d_in[0];  // [BATCH, 100]
    const float* A_real   = (const float*)d_in[1];  // [2,10,10,100]
    const float* A_imag   = (const float*)d_in[2];  // [2,10,10,100]
    const float* psi_real = (const float*)d_in[3];  // [10]
    const float* psi_imag = (const float*)d_in[4];  // [10]

    int batch  = in_sizes[0] / 100;
    int ntiles = (batch + TILE - 1) / TILE;

    static bool attr_done = false;
    if (!attr_done) {
        cudaFuncSetAttribute(fused_kernel,
                             cudaFuncAttributeMaxDynamicSharedMemorySize, SMEM_BYTES);
        attr_done = true;
    }

    int nblk = 296;                              // 2 blocks per SM
    if (nblk > ntiles) nblk = ntiles;
    fused_kernel<<<nblk, BLOCK_T, SMEM_BYTES>>>(reinterpret_cast<const float4*>(x),
                                                A_real, A_imag,
                                                psi_real, psi_imag,
                                                reinterpret_cast<float2*>(d_out),
                                                batch, ntiles);
}

// round 6
// speedup vs baseline: 1.0934x; 1.0934x over previous
#include <cuda_runtime.h>
#include <cstdint>

// Stage-1 partials: g_Mpart[k*1000 + i*100 + a]; gemv sums over i.
__device__ __align__(16) float g_Mpart[2000];

// ---------------- Stage 1: 20 blocks, one per (k,i) ----------------
__global__ void compute_Mpart_kernel(const float* __restrict__ A_real,
                                     const float* __restrict__ A_imag,
                                     const float* __restrict__ psi_real,
                                     const float* __restrict__ psi_imag) {
    __shared__ float pr[10], pi[10];
    if (threadIdx.x < 10) {
        pr[threadIdx.x] = psi_real[threadIdx.x];
        pi[threadIdx.x] = psi_imag[threadIdx.x];
    }
    __syncthreads();

    int ki = blockIdx.x;          // 0..19 -> (k, i)
    int k  = ki / 10;
    int i  = ki - k * 10;
    int a  = threadIdx.x;
    if (a < 100) {
        float acc = 0.0f;
        #pragma unroll
        for (int j = 0; j < 10; j++) {
            float Pre = pr[i] * pr[j] + pi[i] * pi[j];
            float Pim = pr[i] * pi[j] - pi[i] * pr[j];
            int idx = ((k * 10 + i) * 10 + j) * 100 + a;
            acc = fmaf(Pre, A_real[idx], acc);
            acc = fmaf(-Pim, A_imag[idx], acc);
        }
        g_Mpart[k * 1000 + i * 100 + a] = acc;
    }
    // Let the dependent gemv launch as soon as partials are written.
    cudaTriggerProgrammaticLaunchCompletion();
}

// ---------------- Stage 2: warp-private pipelined GEMV ----------------
#define WARPS_PB   8
#define BLOCK_T    256
#define ROWS_W     32                          // rows per warp-stage
#define F4_W       (ROWS_W * 25)               // 800 float4 per stage
#define STAGES     2
#define SMEM_BYTES (WARPS_PB * STAGES * F4_W * 16)   // 204800 B

__device__ __forceinline__ void cp_async16(void* smem_dst, const void* gsrc) {
    uint32_t d = (uint32_t)__cvta_generic_to_shared(smem_dst);
    asm volatile("cp.async.cg.shared.global [%0], [%1], 16;\n" :: "r"(d), "l"(gsrc));
}

__global__ void __launch_bounds__(BLOCK_T, 1) gemv_kernel(
    const float4* __restrict__ x4,
    float2* __restrict__ out,
    int batch, int nchunks)
{
    extern __shared__ __align__(128) float4 sx[];   // [WARPS_PB][STAGES][F4_W]
    __shared__ __align__(16) float sMf[200];

    int tid  = threadIdx.x;
    int wid  = tid >> 5;
    int lane = tid & 31;

    float4* ws = sx + (size_t)wid * (STAGES * F4_W);

    int gwarp  = blockIdx.x * WARPS_PB + wid;
    int stride = gridDim.x * WARPS_PB;

    // Issue one 32-row chunk into warp-stage s (fully coalesced, 25 cp.async/lane).
    auto issue = [&](int chunk, int s) {
        const float4* src = x4 + (size_t)chunk * F4_W;
        float4* dst = ws + s * F4_W;
        int limit = batch * 25 - chunk * F4_W;       // valid f4 in this chunk
        if (limit >= F4_W) {
            #pragma unroll
            for (int r = 0; r < 25; r++)
                cp_async16(dst + r * 32 + lane, src + r * 32 + lane);
        } else {
            #pragma unroll
            for (int r = 0; r < 25; r++) {
                int i = r * 32 + lane;
                if (i < limit) cp_async16(dst + i, src + i);
            }
        }
        asm volatile("cp.async.commit_group;\n");
    };

    // Prologue: enqueue both stages (reads x only — legal before the PDL sync).
    if (gwarp < nchunks)          issue(gwarp, 0);
    else                          asm volatile("cp.async.commit_group;\n");
    if (gwarp + stride < nchunks) issue(gwarp + stride, 1);
    else                          asm volatile("cp.async.commit_group;\n");

    // Wait for stage-1 grid (PDL), then fold partials into smem M.
    cudaGridDependencySynchronize();
    if (tid < 200) {
        int k = tid / 100, a = tid - k * 100;
        float acc = 0.0f;
        #pragma unroll
        for (int i = 0; i < 10; i++) acc += g_Mpart[k * 1000 + i * 100 + a];
        sMf[tid] = acc;
    }
    __syncthreads();
    const float4* sM4 = reinterpret_cast<const float4*>(sMf);   // [50]

    // Steady loop: warp-private, no block barriers.
    int cnt = 0;
    for (int c = gwarp; c < nchunks; c += stride, cnt++) {
        int s = cnt & 1;
        asm volatile("cp.async.wait_group 1;\n");
        __syncwarp();

        int row = c * ROWS_W + lane;
        const float4* xr = ws + s * F4_W + lane * 25;
        float s0 = 0.0f, s1 = 0.0f;
        #pragma unroll
        for (int i = 0; i < 25; i++) {
            float4 v  = xr[i];
            float4 m0 = sM4[i];
            float4 m1 = sM4[25 + i];
            s0 = fmaf(v.x, m0.x, s0); s0 = fmaf(v.y, m0.y, s0);
            s0 = fmaf(v.z, m0.z, s0); s0 = fmaf(v.w, m0.w, s0);
            s1 = fmaf(v.x, m1.x, s1); s1 = fmaf(v.y, m1.y, s1);
            s1 = fmaf(v.z, m1.z, s1); s1 = fmaf(v.w, m1.w, s1);
        }
        if (row < batch) out[row] = make_float2(s0, s1);
        __syncwarp();                      // stage s consumed by whole warp

        int cn = c + STAGES * stride;
        if (cn < nchunks) issue(cn, s);
        else              asm volatile("cp.async.commit_group;\n");
    }
}

extern "C" void kernel_launch(void* const* d_in, const int* in_sizes, int n_in,
                              void* d_out, int out_size) {
    const float* x        = (const float*)d_in[0];  // [BATCH, 100]
    const float* A_real   = (const float*)d_in[1];  // [2,10,10,100]
    const float* A_imag   = (const float*)d_in[2];  // [2,10,10,100]
    const float* psi_real = (const float*)d_in[3];  // [10]
    const float* psi_imag = (const float*)d_in[4];  // [10]

    int batch   = in_sizes[0] / 100;
    int nchunks = (batch + ROWS_W - 1) / ROWS_W;

    static bool attr_done = false;
    if (!attr_done) {
        cudaFuncSetAttribute(gemv_kernel,
                             cudaFuncAttributeMaxDynamicSharedMemorySize, SMEM_BYTES);
        attr_done = true;
    }

    compute_Mpart_kernel<<<20, 128>>>(A_real, A_imag, psi_real, psi_imag);

    // Launch gemv with programmatic dependent launch so its prologue overlaps
    // stage 1. Stream order still guarantees correctness if PDL is ignored.
    cudaLaunchAttribute attrs[1];
    attrs[0].id = cudaLaunchAttributeProgrammaticStreamSerialization;
    attrs[0].val.programmaticStreamSerializationAllowed = 1;

    cudaLaunchConfig_t cfg = {};
    cfg.gridDim  = dim3(148);
    cfg.blockDim = dim3(BLOCK_T);
    cfg.dynamicSmemBytes = SMEM_BYTES;
    cfg.stream = 0;
    cfg.attrs = attrs;
    cfg.numAttrs = 1;

    cudaLaunchKernelEx(&cfg, gemv_kernel,
                       reinterpret_cast<const float4*>(x),
                       reinterpret_cast<float2*>(d_out),
                       batch, nchunks);
}

// round 7
// speedup vs baseline: 1.1006x; 1.0065x over previous
#include <cuda_runtime.h>
#include <cstdint>

// Stage-1 partials: g_Mpart[k*1000 + i*100 + a]; gemv sums over i.
__device__ __align__(16) float g_Mpart[2000];

// ---------------- Stage 1: 20 blocks, one per (k,i) ----------------
__global__ void compute_Mpart_kernel(const float* __restrict__ A_real,
                                     const float* __restrict__ A_imag,
                                     const float* __restrict__ psi_real,
                                     const float* __restrict__ psi_imag) {
    __shared__ float pr[10], pi[10];
    if (threadIdx.x < 10) {
        pr[threadIdx.x] = psi_real[threadIdx.x];
        pi[threadIdx.x] = psi_imag[threadIdx.x];
    }
    __syncthreads();

    int ki = blockIdx.x;          // 0..19 -> (k, i)
    int k  = ki / 10;
    int i  = ki - k * 10;
    int a  = threadIdx.x;
    if (a < 100) {
        float acc = 0.0f;
        #pragma unroll
        for (int j = 0; j < 10; j++) {
            float Pre = pr[i] * pr[j] + pi[i] * pi[j];
            float Pim = pr[i] * pi[j] - pi[i] * pr[j];
            int idx = ((k * 10 + i) * 10 + j) * 100 + a;
            acc = fmaf(Pre, A_real[idx], acc);
            acc = fmaf(-Pim, A_imag[idx], acc);
        }
        g_Mpart[k * 1000 + i * 100 + a] = acc;
    }
    cudaTriggerProgrammaticLaunchCompletion();
}

// ---------------- Stage 2: warp-private TMA-pipelined GEMV ----------------
#define WARPS_PB   8
#define BLOCK_T    256
#define ROWS_W     32                          // rows per warp-stage chunk
#define F4_W       (ROWS_W * 25)               // 800 float4 per stage
#define CHUNK_B    (F4_W * 16)                 // 12800 bytes
#define STAGES     2
#define SMEM_BYTES (WARPS_PB * STAGES * CHUNK_B)     // 204800 B

__device__ __forceinline__ void mbar_wait(unsigned mbar, unsigned phase) {
    unsigned done;
    asm volatile("{\n\t.reg .pred p;\n\t"
                 "mbarrier.try_wait.parity.acquire.cta.shared::cta.b64 p, [%1], %2;\n\t"
                 "selp.b32 %0, 1, 0, p;\n\t}"
                 : "=r"(done) : "r"(mbar), "r"(phase) : "memory");
    while (!done) {
        asm volatile("{\n\t.reg .pred p;\n\t"
                     "mbarrier.try_wait.parity.acquire.cta.shared::cta.b64 p, [%1], %2, 0x989680;\n\t"
                     "selp.b32 %0, 1, 0, p;\n\t}"
                     : "=r"(done) : "r"(mbar), "r"(phase) : "memory");
    }
}

__global__ void __launch_bounds__(BLOCK_T, 1) gemv_kernel(
    const float* __restrict__ x,
    float2* __restrict__ out,
    int batch, int nchunks)
{
    extern __shared__ __align__(128) float4 sx[];   // [WARPS_PB][STAGES][F4_W]
    __shared__ __align__(16) float sMf[200];
    __shared__ __align__(8) unsigned long long mbar_store[WARPS_PB * STAGES];

    int tid  = threadIdx.x;
    int wid  = tid >> 5;
    int lane = tid & 31;

    unsigned mbar_base = (unsigned)__cvta_generic_to_shared(&mbar_store[0]);
    unsigned wmbar = mbar_base + (wid * STAGES) * 8;        // this warp's 2 barriers
    float4* ws = sx + (size_t)wid * (STAGES * F4_W);

    if (tid < WARPS_PB * STAGES)
        asm volatile("mbarrier.init.shared.b64 [%0], %1;"
                     :: "r"(mbar_base + tid * 8), "r"(1) : "memory");
    __syncthreads();

    int gwarp  = blockIdx.x * WARPS_PB + wid;
    int stride = gridDim.x * WARPS_PB;

    // Issue one chunk into warp-stage s via a single bulk copy (lane 0 only).
    auto issue = [&](int chunk, int s) {
        if (lane == 0) {
            int rows = batch - chunk * ROWS_W;
            if (rows > ROWS_W) rows = ROWS_W;
            unsigned bytes = (unsigned)rows * 400u;
            unsigned mb = wmbar + s * 8;
            asm volatile("mbarrier.arrive.expect_tx.shared.b64 _, [%0], %1;"
                         :: "r"(mb), "r"(bytes) : "memory");
            unsigned dst = (unsigned)__cvta_generic_to_shared(ws + s * F4_W);
            const float* src = x + (size_t)chunk * (ROWS_W * 100);
            asm volatile("cp.async.bulk.shared::cta.global.mbarrier::complete_tx::bytes "
                         "[%0], [%1], %2, [%3];"
                         :: "r"(dst), "l"(src), "r"(bytes), "r"(mb) : "memory");
        }
    };

    // Prologue: enqueue both stages (reads x only — legal before PDL sync).
    if (gwarp < nchunks)          issue(gwarp, 0);
    if (gwarp + stride < nchunks) issue(gwarp + stride, 1);

    // Wait for stage-1 grid (PDL), then fold partials into smem M.
    cudaGridDependencySynchronize();
    if (tid < 200) {
        int k = tid / 100, a = tid - k * 100;
        float acc = 0.0f;
        #pragma unroll
        for (int i = 0; i < 10; i++) acc += g_Mpart[k * 1000 + i * 100 + a];
        sMf[tid] = acc;
    }
    __syncthreads();
    const float4* sM4 = reinterpret_cast<const float4*>(sMf);   // [50]

    // Steady loop: warp-private, no block barriers.
    int cnt = 0;
    for (int c = gwarp; c < nchunks; c += stride, cnt++) {
        int s = cnt & 1;
        unsigned phase = (cnt >> 1) & 1;
        mbar_wait(wmbar + s * 8, phase);

        int row = c * ROWS_W + lane;
        const float4* xr = ws + s * F4_W + lane * 25;
        float s0 = 0.0f, s1 = 0.0f;
        #pragma unroll
        for (int i = 0; i < 25; i++) {
            float4 v  = xr[i];
            float4 m0 = sM4[i];
            float4 m1 = sM4[25 + i];
            s0 = fmaf(v.x, m0.x, s0); s0 = fmaf(v.y, m0.y, s0);
            s0 = fmaf(v.z, m0.z, s0); s0 = fmaf(v.w, m0.w, s0);
            s1 = fmaf(v.x, m1.x, s1); s1 = fmaf(v.y, m1.y, s1);
            s1 = fmaf(v.z, m1.z, s1); s1 = fmaf(v.w, m1.w, s1);
        }
        if (row < batch) out[row] = make_float2(s0, s1);
        __syncwarp();                      // whole warp done reading stage s

        int cn = c + STAGES * stride;
        if (cn < nchunks) issue(cn, s);
    }
}

extern "C" void kernel_launch(void* const* d_in, const int* in_sizes, int n_in,
                              void* d_out, int out_size) {
    const float* x        = (const float*)d_in[0];  // [BATCH, 100]
    const float* A_real   = (const float*)d_in[1];  // [2,10,10,100]
    const float* A_imag   = (const float*)d_in[2];  // [2,10,10,100]
    const float* psi_real = (const float*)d_in[3];  // [10]
    const float* psi_imag = (const float*)d_in[4];  // [10]

    int batch   = in_sizes[0] / 100;
    int nchunks = (batch + ROWS_W - 1) / ROWS_W;

    static bool attr_done = false;
    if (!attr_done) {
        cudaFuncSetAttribute(gemv_kernel,
                             cudaFuncAttributeMaxDynamicSharedMemorySize, SMEM_BYTES);
        attr_done = true;
    }

    compute_Mpart_kernel<<<20, 128>>>(A_real, A_imag, psi_real, psi_imag);

    cudaLaunchAttribute attrs[1];
    attrs[0].id = cudaLaunchAttributeProgrammaticStreamSerialization;
    attrs[0].val.programmaticStreamSerializationAllowed = 1;

    cudaLaunchConfig_t cfg = {};
    cfg.gridDim  = dim3(148);
    cfg.blockDim = dim3(BLOCK_T);
    cfg.dynamicSmemBytes = SMEM_BYTES;
    cfg.stream = 0;
    cfg.attrs = attrs;
    cfg.numAttrs = 1;

    cudaLaunchKernelEx(&cfg, gemv_kernel, x,
                       reinterpret_cast<float2*>(d_out),
                       batch, nchunks);
}